// round 9
// baseline (speedup 1.0000x reference)
#include <cuda_runtime.h>
#include <cuda_bf16.h>

#define NBINS 36
#define PS 32
#define BLK 128
#define HW 64                    // hist width: 2 half-warps x 32 lanes
#define TWO_PI_F 6.2831855f      // f32(2*pi)
#define PI_F     3.1415927f      // f32(pi)
#define FULLM 0xffffffffu

__device__ __forceinline__ float sqrt_approx(float x) {
    float r; asm("sqrt.approx.f32 %0,%1;" : "=f"(r) : "f"(x)); return r;
}
// patch-scoped barrier: patch pw uses named barrier 1+pw over its 64 threads
__device__ __forceinline__ void patch_bar(int pw) {
    asm volatile("bar.sync %0, 64;" :: "r"(1 + pw) : "memory");
}

__global__ __launch_bounds__(BLK, 9)   // 56-reg cap; smem 23.1KB -> 9 CTAs/SM
void OrientationFinder_83193516523885_kernel(
    const float* __restrict__ x,
    const float* __restrict__ gxw,
    const float* __restrict__ gyw,
    const float* __restrict__ smw,
    const float* __restrict__ gk,
    float* __restrict__ out,
    int B)
{
    __shared__ __align__(16) float gksm[PS * 36];        // gk, padded stride 36
    __shared__ __align__(16) float hist2[2][NBINS * HW]; // per-patch hist (tile overlaid)
    __shared__ float scratch[2][2][40];                  // [patch][half][bin] partials

    const int t  = threadIdx.x;
    const int pw = t >> 6;            // patch within block (0..1)
    const int tt = t & 63;            // thread within patch
    const int w2 = tt >> 5;           // column-half (0..1)
    const int l  = t & 31;            // lane = row

    // ---- cooperative gk staging (all 128 threads) ----
    {
        const float4* g4 = (const float4*)gk;
        #pragma unroll
        for (int j = 0; j < 2; ++j) {
            int m = t + BLK * j;
            float4 v = g4[m];
            *(float4*)&gksm[(m >> 3) * 36 + ((m & 7) << 2)] = v;
        }
    }

    const long long p = (long long)blockIdx.x * 2 + pw;
    float* hist = hist2[pw];

    // ---- coalesced global load: 64 threads x 4 float4 = one patch ----
    float4 vb[4];
    if (p < B) {
        const float4* xv = (const float4*)(x + p * (PS * PS));
        #pragma unroll
        for (int j = 0; j < 4; ++j) vb[j] = xv[tt + 64 * j];
    }
    const float w0x = gxw[0], w1x = gxw[1], w2x = gxw[2];
    const float w0y = gyw[0], w1y = gyw[1], w2y = gyw[2];
    const float m0 = smw[0], m1 = smw[1], m2 = smw[2];
    const bool fx = (w1x == 0.0f);    // uniform fast-path (bit-safe, see prior rounds)
    const bool fy = (w1y == 0.0f);

    __syncthreads();                  // gksm visible

    // ---- redistribute to row-major tile (overlaid on hist; 1152 < 2304 floats) ----
    float* tile = hist;               // stride-36 rows
    if (p < B) {
        #pragma unroll
        for (int j = 0; j < 4; ++j) {
            int m = tt + 64 * j;
            *(float4*)&tile[(m >> 3) * 36 + ((m & 7) << 2)] = vb[j];
        }
    }
    patch_bar(pw);                    // cross-warp tile writes visible

    // ---- lane reads its 16-column strip of row l, plus the 2 edge scalars ----
    float c[16];
    {
        const int cb = 16 * w2;       // global col base
        #pragma unroll
        for (int j = 0; j < 4; ++j) {
            float4 v = *(const float4*)&tile[l * 36 + cb + 4 * j];
            c[4*j] = v.x; c[4*j+1] = v.y; c[4*j+2] = v.z; c[4*j+3] = v.w;
        }
    }
    const float lf_edge = (w2 == 0) ? c[0]  : tile[l * 36 + 15];  // col0 replicates
    const float rt_edge = (w2 == 1) ? c[15] : tile[l * 36 + 16];  // col31 replicates
    patch_bar(pw);                    // all tile reads done before overlay is destroyed

    // ---- zero hist: 2304 floats = 576 float4 over 64 threads ----
    {
        float4 z = make_float4(0.f, 0.f, 0.f, 0.f);
        #pragma unroll
        for (int j = 0; j < 9; ++j)
            *(float4*)&hist[(tt + 64 * j) << 2] = z;
    }
    patch_bar(pw);                    // zeroed before scatter

    // ---- main loop: 2 chunks x 8 pixels; compute unconditional, RMW predicated ----
    const int colw = (w2 << 5) + l;   // private hist column (bank = lane)
    #pragma unroll
    for (int k = 0; k < 2; ++k) {
        float4 ga = *(const float4*)&gksm[l * 36 + 16 * w2 + 8 * k];
        float4 gb = *(const float4*)&gksm[l * 36 + 16 * w2 + 8 * k + 4];
        float gg[8] = {ga.x, ga.y, ga.z, ga.w, gb.x, gb.y, gb.z, gb.w};
        #pragma unroll
        for (int i = 0; i < 8; ++i) {
            const int q = 8 * k + i;  // local col 0..15
            float up = __shfl_up_sync(FULLM, c[q], 1);    // lane 0 -> self (replicate)
            float dn = __shfl_down_sync(FULLM, c[q], 1);  // lane 31 -> self
            float lf = (q > 0)  ? c[q - 1] : lf_edge;
            float rt = (q < 15) ? c[q + 1] : rt_edge;
            float gx = __fadd_rn(__fmul_rn(w0x, lf), __fmul_rn(w2x, rt));
            if (!fx) gx = __fadd_rn(__fadd_rn(__fmul_rn(w0x, lf),
                                              __fmul_rn(w1x, c[q])),
                                    __fmul_rn(w2x, rt));
            float gy = __fadd_rn(__fmul_rn(w0y, up), __fmul_rn(w2y, dn));
            if (!fy) gy = __fadd_rn(__fadd_rn(__fmul_rn(w0y, up),
                                              __fmul_rn(w1y, c[q])),
                                    __fmul_rn(w2y, dn));
            float s  = __fadd_rn(__fadd_rn(__fmul_rn(gx, gx), __fmul_rn(gy, gy)),
                                 1e-10f);
            float m  = __fmul_rn(sqrt_approx(s), gg[i]);

            float o = atan2f(gy, gx);                     // bit-exact libdevice path
            if (o < 0.f) o = __fadd_rn(o, TWO_PI_F);      // jnp.mod(ori, 2pi)
            float ob = __fdiv_rn(__fmul_rn(36.f, o), TWO_PI_F);
            float bf = floorf(ob);
            int b = (int)bf;
            if (b > NBINS - 1) b -= NBINS;                // ob == 36.0 edge
            float wgt = __fmul_rn(__fsub_rn(1.f, __fsub_rn(ob, bf)), m);
            const int a = b * HW + colw;

            if (m > 0.001f)                               // short arm -> @P predication
                hist[a] = __fadd_rn(hist[a], wgt);
        }
    }
    patch_bar(pw);

    // ---- reduction: each half-warp sums its own 32 columns (diagonal, conflict-free) ----
    {
        float s = 0.f, e = 0.f;
        #pragma unroll
        for (int cc = 0; cc < 32; ++cc)
            s = __fadd_rn(s, hist[l * HW + (w2 << 5) + ((l + cc) & 31)]);
        if (l < 4) {
            #pragma unroll
            for (int cc = 0; cc < 32; ++cc)
                e = __fadd_rn(e, hist[(32 + l) * HW + (w2 << 5) + ((l + cc) & 31)]);
        }
        scratch[pw][w2][l] = s;
        if (l < 4) scratch[pw][w2][32 + l] = e;
    }
    patch_bar(pw);

    // ---- epilogue on half-warp 0 of each patch ----
    if (w2 == 0) {
        float s = __fmul_rn(scratch[pw][0][l] + scratch[pw][1][l], 0.0009765625f);
        float e = 0.f;
        if (l < 4)
            e = __fmul_rn(scratch[pw][0][32 + l] + scratch[pw][1][32 + l],
                          0.0009765625f);

        float hm  = __shfl_up_sync(FULLM, s, 1);
        float hp  = __shfl_down_sync(FULLM, s, 1);
        float e0  = __shfl_sync(FULLM, e, 0);
        float s31 = __shfl_sync(FULLM, s, 31);
        float em  = __shfl_up_sync(FULLM, e, 1);
        float ep  = __shfl_down_sync(FULLM, e, 1);
        if (l == 0)  hm = 0.f;            // zero pad left
        if (l == 31) hp = e0;             // h[32]
        float v1 = __fadd_rn(__fadd_rn(__fmul_rn(m0, hm), __fmul_rn(m1, s)),
                             __fmul_rn(m2, hp));
        int i1 = l;
        if (l < 4) {                      // bins 32..35
            float hm2 = (l == 0) ? s31 : em;
            float hp2 = (l == 3) ? 0.f : ep;
            float v2 = __fadd_rn(__fadd_rn(__fmul_rn(m0, hm2), __fmul_rn(m1, e)),
                                 __fmul_rn(m2, hp2));
            if (v2 > v1) { v1 = v2; i1 = 32 + l; }   // tie keeps smaller index
        }
        #pragma unroll
        for (int off = 16; off > 0; off >>= 1) {
            float ov = __shfl_xor_sync(FULLM, v1, off);
            int   oi = __shfl_xor_sync(FULLM, i1, off);
            if (ov > v1 || (ov == v1 && oi < i1)) { v1 = ov; i1 = oi; }
        }
        if (l == 0 && p < B) {
            float fi = (float)i1;
            out[p] = -__fsub_rn(__fdiv_rn(__fmul_rn(TWO_PI_F, fi), 36.f), PI_F);
        }
    }
}

extern "C" void kernel_launch(void* const* d_in, const int* in_sizes, int n_in,
                              void* d_out, int out_size)
{
    const float* x   = (const float*)d_in[0];
    const float* gxw = (const float*)d_in[1];
    const float* gyw = (const float*)d_in[2];
    const float* smw = (const float*)d_in[3];
    const float* gk  = (const float*)d_in[4];
    float* out = (float*)d_out;

    int B = in_sizes[0] / (PS * PS);
    int grid = (B + 1) / 2;
    OrientationFinder_83193516523885_kernel<<<grid, BLK>>>(x, gxw, gyw, smw, gk, out, B);
}

// round 10
// speedup vs baseline: 1.0447x; 1.0447x over previous
#include <cuda_runtime.h>
#include <cuda_bf16.h>

#define NBINS 36
#define PS 32
#define BLK 128
#define HW 64                    // hist width: 2 half-warps x 32 columns
#define TWO_PI_F 6.2831855f      // f32(2*pi)
#define PI_F     3.1415927f      // f32(pi)
#define FULLM 0xffffffffu

__device__ __forceinline__ float sqrt_approx(float x) {
    float r; asm("sqrt.approx.f32 %0,%1;" : "=f"(r) : "f"(x)); return r;
}

__global__ __launch_bounds__(BLK, 9)   // 56-reg cap; smem ~19.6KB; 1 barrier -> 9 CTAs
void OrientationFinder_83193516523885_kernel(
    const float* __restrict__ x,
    const float* __restrict__ gxw,
    const float* __restrict__ gyw,
    const float* __restrict__ smw,
    const float* __restrict__ gk,
    float* __restrict__ out,
    int B)
{
    __shared__ __align__(16) float hist2[2][NBINS * HW]; // per-patch hist, 18.4KB
    __shared__ float edge[2][2][32];                     // [patch][half][row] edge cols
    __shared__ float scratch[2][2][40];                  // [patch][half][bin] partials

    const int t  = threadIdx.x;
    const int pw = t >> 6;            // patch within block (0..1)
    const int tt = t & 63;            // thread within patch
    const int w2 = tt >> 5;           // column-half (0..1)
    const int l  = t & 31;            // lane = row

    const long long p = (long long)blockIdx.x * 2 + pw;
    float* hist = hist2[pw];
    const int cb = 16 * w2;           // global column base of this half

    // ---- direct row-strip load: lane l owns row l, cols [cb, cb+16) ----
    // (each 128B x-line is fully consumed across j; gk is 4KB L1-resident)
    float c[16];
    float gg[16];
    {
        const float* xr = x + p * (PS * PS) + l * PS + cb;
        const float* gr = gk + l * PS + cb;
        #pragma unroll
        for (int j = 0; j < 4; ++j) {
            float4 v = __ldg((const float4*)(xr + 4 * j));
            c[4*j] = v.x; c[4*j+1] = v.y; c[4*j+2] = v.z; c[4*j+3] = v.w;
            float4 g = __ldg((const float4*)(gr + 4 * j));
            gg[4*j] = g.x; gg[4*j+1] = g.y; gg[4*j+2] = g.z; gg[4*j+3] = g.w;
        }
    }
    const float w0x = gxw[0], w1x = gxw[1], w2x = gxw[2];
    const float w0y = gyw[0], w1y = gyw[1], w2y = gyw[2];
    const float m0 = smw[0], m1 = smw[1], m2 = smw[2];
    const bool fx = (w1x == 0.0f);    // uniform fast-path (bit-safe, see prior rounds)
    const bool fy = (w1y == 0.0f);

    // cross-warp edge exchange: half 0 exports col 15, half 1 exports col 16
    edge[pw][w2][l] = (w2 == 0) ? c[15] : c[0];

    // ---- zero hist: 2304 floats = 576 float4 over 64 patch-threads ----
    {
        float4 z = make_float4(0.f, 0.f, 0.f, 0.f);
        #pragma unroll
        for (int j = 0; j < 9; ++j)
            *(float4*)&hist[(tt + 64 * j) << 2] = z;
    }
    __syncthreads();                  // edges + zeroed hist visible

    const float lf_edge = (w2 == 0) ? c[0]  : edge[pw][0][l];  // col -1 replicate / col 15
    const float rt_edge = (w2 == 1) ? c[15] : edge[pw][1][l];  // col 16 / col 32 replicate

    // ---- main loop: 16 px/lane; compute unconditional, RMW predicated ----
    const int colw = (w2 << 5) + l;   // private hist column (bank = lane)
    #pragma unroll
    for (int q = 0; q < 16; ++q) {
        float up = __shfl_up_sync(FULLM, c[q], 1);    // lane 0 -> self (replicate)
        float dn = __shfl_down_sync(FULLM, c[q], 1);  // lane 31 -> self
        float lf = (q > 0)  ? c[q - 1] : lf_edge;
        float rt = (q < 15) ? c[q + 1] : rt_edge;
        float gx = __fadd_rn(__fmul_rn(w0x, lf), __fmul_rn(w2x, rt));
        if (!fx) gx = __fadd_rn(__fadd_rn(__fmul_rn(w0x, lf),
                                          __fmul_rn(w1x, c[q])),
                                __fmul_rn(w2x, rt));
        float gy = __fadd_rn(__fmul_rn(w0y, up), __fmul_rn(w2y, dn));
        if (!fy) gy = __fadd_rn(__fadd_rn(__fmul_rn(w0y, up),
                                          __fmul_rn(w1y, c[q])),
                                __fmul_rn(w2y, dn));
        float s  = __fadd_rn(__fadd_rn(__fmul_rn(gx, gx), __fmul_rn(gy, gy)),
                             1e-10f);
        float m  = __fmul_rn(sqrt_approx(s), gg[q]);

        float o = atan2f(gy, gx);                     // bit-exact libdevice path
        if (o < 0.f) o = __fadd_rn(o, TWO_PI_F);      // jnp.mod(ori, 2pi)
        float ob = __fdiv_rn(__fmul_rn(36.f, o), TWO_PI_F);
        float bf = floorf(ob);
        int b = (int)bf;
        if (b > NBINS - 1) b -= NBINS;                // ob == 36.0 edge
        float wgt = __fmul_rn(__fsub_rn(1.f, __fsub_rn(ob, bf)), m);
        const int a = b * HW + colw;

        if (m > 0.001f)                               // short arm -> @P predication
            hist[a] = __fadd_rn(hist[a], wgt);
    }
    __syncthreads();

    // ---- reduction: each half sums its own 32 columns (diagonal, conflict-free) ----
    {
        float s = 0.f, e = 0.f;
        #pragma unroll
        for (int cc = 0; cc < 32; ++cc)
            s = __fadd_rn(s, hist[l * HW + (w2 << 5) + ((l + cc) & 31)]);
        if (l < 4) {
            #pragma unroll
            for (int cc = 0; cc < 32; ++cc)
                e = __fadd_rn(e, hist[(32 + l) * HW + (w2 << 5) + ((l + cc) & 31)]);
        }
        scratch[pw][w2][l] = s;
        if (l < 4) scratch[pw][w2][32 + l] = e;
    }
    __syncthreads();

    // ---- epilogue on half 0 of each patch ----
    if (w2 == 0) {
        float s = __fmul_rn(__fadd_rn(scratch[pw][0][l], scratch[pw][1][l]),
                            0.0009765625f);           // /1024 exact
        float e = 0.f;
        if (l < 4)
            e = __fmul_rn(__fadd_rn(scratch[pw][0][32 + l], scratch[pw][1][32 + l]),
                          0.0009765625f);

        float hm  = __shfl_up_sync(FULLM, s, 1);
        float hp  = __shfl_down_sync(FULLM, s, 1);
        float e0  = __shfl_sync(FULLM, e, 0);
        float s31 = __shfl_sync(FULLM, s, 31);
        float em  = __shfl_up_sync(FULLM, e, 1);
        float ep  = __shfl_down_sync(FULLM, e, 1);
        if (l == 0)  hm = 0.f;            // zero pad left
        if (l == 31) hp = e0;             // h[32]
        float v1 = __fadd_rn(__fadd_rn(__fmul_rn(m0, hm), __fmul_rn(m1, s)),
                             __fmul_rn(m2, hp));
        int i1 = l;
        if (l < 4) {                      // bins 32..35
            float hm2 = (l == 0) ? s31 : em;
            float hp2 = (l == 3) ? 0.f : ep;
            float v2 = __fadd_rn(__fadd_rn(__fmul_rn(m0, hm2), __fmul_rn(m1, e)),
                                 __fmul_rn(m2, hp2));
            if (v2 > v1) { v1 = v2; i1 = 32 + l; }   // tie keeps smaller index
        }
        #pragma unroll
        for (int off = 16; off > 0; off >>= 1) {
            float ov = __shfl_xor_sync(FULLM, v1, off);
            int   oi = __shfl_xor_sync(FULLM, i1, off);
            if (ov > v1 || (ov == v1 && oi < i1)) { v1 = ov; i1 = oi; }
        }
        if (l == 0 && p < B) {
            float fi = (float)i1;
            out[p] = -__fsub_rn(__fdiv_rn(__fmul_rn(TWO_PI_F, fi), 36.f), PI_F);
        }
    }
}

extern "C" void kernel_launch(void* const* d_in, const int* in_sizes, int n_in,
                              void* d_out, int out_size)
{
    const float* x   = (const float*)d_in[0];
    const float* gxw = (const float*)d_in[1];
    const float* gyw = (const float*)d_in[2];
    const float* smw = (const float*)d_in[3];
    const float* gk  = (const float*)d_in[4];
    float* out = (float*)d_out;

    int B = in_sizes[0] / (PS * PS);
    int grid = (B + 1) / 2;
    OrientationFinder_83193516523885_kernel<<<grid, BLK>>>(x, gxw, gyw, smw, gk, out, B);
}

// round 11
// speedup vs baseline: 1.2176x; 1.1655x over previous
#include <cuda_runtime.h>
#include <cuda_bf16.h>

#define NBINS 36
#define PS 32
#define BLK 128
#define HW 64                    // hist width: 2 column-halves x 32 lanes
#define TWO_PI_F 6.2831855f      // f32(2*pi)
#define PI_F     3.1415927f      // f32(pi)
#define FULLM 0xffffffffu

__device__ __forceinline__ float sqrt_approx(float x) {
    float r; asm("sqrt.approx.f32 %0,%1;" : "=f"(r) : "f"(x)); return r;
}

__global__ __launch_bounds__(BLK, 9)   // 56-reg cap; smem ~23.6KB; 1 barrier slot
void OrientationFinder_83193516523885_kernel(
    const float* __restrict__ x,
    const float* __restrict__ gxw,
    const float* __restrict__ gyw,
    const float* __restrict__ smw,
    const float* __restrict__ gk,
    float* __restrict__ out,
    int B)
{
    __shared__ __align__(16) float gksm[PS * 36];        // gk, padded stride 36 (shared by both patches)
    __shared__ __align__(16) float hist2[2][NBINS * HW]; // per-patch hist (tile overlaid)
    __shared__ float scratch[2][2][40];                  // [patch][half][bin] partials

    const int t  = threadIdx.x;
    const int pw = t >> 6;            // patch within block (0..1)
    const int tt = t & 63;            // thread within patch
    const int w2 = tt >> 5;           // column-half (0..1)
    const int l  = t & 31;            // lane = row

    // ---- cooperative gk staging (all 128 threads, coalesced) ----
    {
        const float4* g4 = (const float4*)gk;
        #pragma unroll
        for (int j = 0; j < 2; ++j) {
            int m = t + BLK * j;
            float4 v = g4[m];
            *(float4*)&gksm[(m >> 3) * 36 + ((m & 7) << 2)] = v;
        }
    }

    const long long p = (long long)blockIdx.x * 2 + pw;
    float* hist = hist2[pw];

    // ---- coalesced global load: 64 threads x 4 float4 = one patch ----
    float4 vb[4];
    if (p < B) {
        const float4* xv = (const float4*)(x + p * (PS * PS));
        #pragma unroll
        for (int j = 0; j < 4; ++j) vb[j] = xv[tt + 64 * j];
    }
    const float w0x = gxw[0], w1x = gxw[1], w2x = gxw[2];
    const float w0y = gyw[0], w1y = gyw[1], w2y = gyw[2];
    const float m0 = smw[0], m1 = smw[1], m2 = smw[2];
    const bool fx = (w1x == 0.0f);    // uniform fast-path (bit-safe, see prior rounds)
    const bool fy = (w1y == 0.0f);

    // ---- redistribute to row-major tile (overlaid on hist; 1152 < 2304 floats) ----
    float* tile = hist;               // stride-36 rows
    if (p < B) {
        #pragma unroll
        for (int j = 0; j < 4; ++j) {
            int m = tt + 64 * j;
            *(float4*)&tile[(m >> 3) * 36 + ((m & 7) << 2)] = vb[j];
        }
    }
    __syncthreads();                  // tile writes + gksm visible

    // ---- lane reads its 16-column strip of row l, plus the 2 edge scalars ----
    float c[16];
    {
        const int cb = 16 * w2;       // global col base
        #pragma unroll
        for (int j = 0; j < 4; ++j) {
            float4 v = *(const float4*)&tile[l * 36 + cb + 4 * j];
            c[4*j] = v.x; c[4*j+1] = v.y; c[4*j+2] = v.z; c[4*j+3] = v.w;
        }
    }
    const float lf_edge = (w2 == 0) ? c[0]  : tile[l * 36 + 15];  // col -1 replicates
    const float rt_edge = (w2 == 1) ? c[15] : tile[l * 36 + 16];  // col 32 replicates
    __syncthreads();                  // all tile reads done before overlay destroyed

    // ---- zero hist: 2304 floats = 576 float4 over 64 patch-threads ----
    {
        float4 z = make_float4(0.f, 0.f, 0.f, 0.f);
        #pragma unroll
        for (int j = 0; j < 9; ++j)
            *(float4*)&hist[(tt + 64 * j) << 2] = z;
    }
    __syncthreads();                  // zeroed before scatter

    // ---- main loop: 2 chunks x 8 px; compute unconditional, RMW predicated ----
    const int colw = (w2 << 5) + l;   // private hist column (bank = lane)
    #pragma unroll
    for (int k = 0; k < 2; ++k) {
        float4 ga = *(const float4*)&gksm[l * 36 + 16 * w2 + 8 * k];
        float4 gb = *(const float4*)&gksm[l * 36 + 16 * w2 + 8 * k + 4];
        float gg[8] = {ga.x, ga.y, ga.z, ga.w, gb.x, gb.y, gb.z, gb.w};
        #pragma unroll
        for (int i = 0; i < 8; ++i) {
            const int q = 8 * k + i;  // local col 0..15
            float up = __shfl_up_sync(FULLM, c[q], 1);    // lane 0 -> self (replicate)
            float dn = __shfl_down_sync(FULLM, c[q], 1);  // lane 31 -> self
            float lf = (q > 0)  ? c[q - 1] : lf_edge;
            float rt = (q < 15) ? c[q + 1] : rt_edge;
            float gx = __fadd_rn(__fmul_rn(w0x, lf), __fmul_rn(w2x, rt));
            if (!fx) gx = __fadd_rn(__fadd_rn(__fmul_rn(w0x, lf),
                                              __fmul_rn(w1x, c[q])),
                                    __fmul_rn(w2x, rt));
            float gy = __fadd_rn(__fmul_rn(w0y, up), __fmul_rn(w2y, dn));
            if (!fy) gy = __fadd_rn(__fadd_rn(__fmul_rn(w0y, up),
                                              __fmul_rn(w1y, c[q])),
                                    __fmul_rn(w2y, dn));
            float s  = __fadd_rn(__fadd_rn(__fmul_rn(gx, gx), __fmul_rn(gy, gy)),
                                 1e-10f);
            float m  = __fmul_rn(sqrt_approx(s), gg[i]);

            float o = atan2f(gy, gx);                     // bit-exact libdevice path
            if (o < 0.f) o = __fadd_rn(o, TWO_PI_F);      // jnp.mod(ori, 2pi)
            float ob = __fdiv_rn(__fmul_rn(36.f, o), TWO_PI_F);
            float bf = floorf(ob);
            int b = (int)bf;
            if (b > NBINS - 1) b -= NBINS;                // ob == 36.0 edge
            float wgt = __fmul_rn(__fsub_rn(1.f, __fsub_rn(ob, bf)), m);
            const int a = b * HW + colw;

            if (m > 0.001f)                               // short arm -> @P predication
                hist[a] = __fadd_rn(hist[a], wgt);
        }
    }
    __syncthreads();

    // ---- reduction: each half sums its own 32 columns (diagonal, conflict-free) ----
    {
        float s = 0.f, e = 0.f;
        #pragma unroll
        for (int cc = 0; cc < 32; ++cc)
            s = __fadd_rn(s, hist[l * HW + (w2 << 5) + ((l + cc) & 31)]);
        if (l < 4) {
            #pragma unroll
            for (int cc = 0; cc < 32; ++cc)
                e = __fadd_rn(e, hist[(32 + l) * HW + (w2 << 5) + ((l + cc) & 31)]);
        }
        scratch[pw][w2][l] = s;
        if (l < 4) scratch[pw][w2][32 + l] = e;
    }
    __syncthreads();

    // ---- epilogue on half 0 of each patch ----
    if (w2 == 0) {
        float s = __fmul_rn(__fadd_rn(scratch[pw][0][l], scratch[pw][1][l]),
                            0.0009765625f);               // /1024 exact
        float e = 0.f;
        if (l < 4)
            e = __fmul_rn(__fadd_rn(scratch[pw][0][32 + l], scratch[pw][1][32 + l]),
                          0.0009765625f);

        float hm  = __shfl_up_sync(FULLM, s, 1);
        float hp  = __shfl_down_sync(FULLM, s, 1);
        float e0  = __shfl_sync(FULLM, e, 0);
        float s31 = __shfl_sync(FULLM, s, 31);
        float em  = __shfl_up_sync(FULLM, e, 1);
        float ep  = __shfl_down_sync(FULLM, e, 1);
        if (l == 0)  hm = 0.f;            // zero pad left
        if (l == 31) hp = e0;             // h[32]
        float v1 = __fadd_rn(__fadd_rn(__fmul_rn(m0, hm), __fmul_rn(m1, s)),
                             __fmul_rn(m2, hp));
        int i1 = l;
        if (l < 4) {                      // bins 32..35
            float hm2 = (l == 0) ? s31 : em;
            float hp2 = (l == 3) ? 0.f : ep;
            float v2 = __fadd_rn(__fadd_rn(__fmul_rn(m0, hm2), __fmul_rn(m1, e)),
                                 __fmul_rn(m2, hp2));
            if (v2 > v1) { v1 = v2; i1 = 32 + l; }   // tie keeps smaller index
        }
        #pragma unroll
        for (int off = 16; off > 0; off >>= 1) {
            float ov = __shfl_xor_sync(FULLM, v1, off);
            int   oi = __shfl_xor_sync(FULLM, i1, off);
            if (ov > v1 || (ov == v1 && oi < i1)) { v1 = ov; i1 = oi; }
        }
        if (l == 0 && p < B) {
            float fi = (float)i1;
            out[p] = -__fsub_rn(__fdiv_rn(__fmul_rn(TWO_PI_F, fi), 36.f), PI_F);
        }
    }
}

extern "C" void kernel_launch(void* const* d_in, const int* in_sizes, int n_in,
                              void* d_out, int out_size)
{
    const float* x   = (const float*)d_in[0];
    const float* gxw = (const float*)d_in[1];
    const float* gyw = (const float*)d_in[2];
    const float* smw = (const float*)d_in[3];
    const float* gk  = (const float*)d_in[4];
    float* out = (float*)d_out;

    int B = in_sizes[0] / (PS * PS);
    int grid = (B + 1) / 2;
    OrientationFinder_83193516523885_kernel<<<grid, BLK>>>(x, gxw, gyw, smw, gk, out, B);
}

// round 12
// speedup vs baseline: 1.2780x; 1.0496x over previous
#include <cuda_runtime.h>
#include <cuda_bf16.h>

#define NBINS 36
#define PS 32
#define BLK 128
#define HW 64                    // hist width: 2 column-halves x 32 lanes
#define TWO_PI_F 6.2831855f      // f32(2*pi)
#define PI_F     3.1415927f      // f32(pi)
#define FULLM 0xffffffffu

__device__ __forceinline__ float sqrt_approx(float x) {
    float r; asm("sqrt.approx.f32 %0,%1;" : "=f"(r) : "f"(x)); return r;
}

__global__ __launch_bounds__(BLK, 9)   // 56-reg cap; smem ~23.6KB; 1 barrier slot
void OrientationFinder_83193516523885_kernel(
    const float* __restrict__ x,
    const float* __restrict__ gxw,
    const float* __restrict__ gyw,
    const float* __restrict__ smw,
    const float* __restrict__ gk,
    float* __restrict__ out,
    int B)
{
    __shared__ __align__(16) float gksm[PS * 36];        // gk, padded stride 36
    __shared__ __align__(16) float hist2[2][NBINS * HW]; // per-patch hist (tile overlaid)
    __shared__ float scratch[2][2][40];                  // [patch][half][bin] partials

    const int t  = threadIdx.x;
    const int pw = t >> 6;            // patch within block (0..1)
    const int tt = t & 63;            // thread within patch
    const int w2 = tt >> 5;           // column-half (0..1)
    const int l  = t & 31;            // lane = row

    // ---- cooperative gk staging (all 128 threads, coalesced) ----
    {
        const float4* g4 = (const float4*)gk;
        #pragma unroll
        for (int j = 0; j < 2; ++j) {
            int m = t + BLK * j;
            float4 v = g4[m];
            *(float4*)&gksm[(m >> 3) * 36 + ((m & 7) << 2)] = v;
        }
    }

    const long long p = (long long)blockIdx.x * 2 + pw;
    float* hist = hist2[pw];

    // ---- coalesced global load: 64 threads x 4 float4 = one patch ----
    float4 vb[4];
    if (p < B) {
        const float4* xv = (const float4*)(x + p * (PS * PS));
        #pragma unroll
        for (int j = 0; j < 4; ++j) vb[j] = xv[tt + 64 * j];
    }
    const float w0x = gxw[0], w1x = gxw[1], w2x = gxw[2];
    const float w0y = gyw[0], w1y = gyw[1], w2y = gyw[2];
    const float m0 = smw[0], m1 = smw[1], m2 = smw[2];
    const bool fx = (w1x == 0.0f);    // uniform fast-path (bit-safe, see prior rounds)
    const bool fy = (w1y == 0.0f);
    // Markstein exactly-rounded constant division setup: r = RN(1/2pi), once.
    const float rcp2pi = __fdiv_rn(1.0f, TWO_PI_F);

    // ---- redistribute to row-major tile (overlaid on hist; 1152 < 2304 floats) ----
    float* tile = hist;               // stride-36 rows
    if (p < B) {
        #pragma unroll
        for (int j = 0; j < 4; ++j) {
            int m = tt + 64 * j;
            *(float4*)&tile[(m >> 3) * 36 + ((m & 7) << 2)] = vb[j];
        }
    }
    __syncthreads();                  // tile writes + gksm visible

    // ---- lane reads its 16-column strip of row l, plus the 2 edge scalars ----
    float c[16];
    {
        const int cb = 16 * w2;       // global col base
        #pragma unroll
        for (int j = 0; j < 4; ++j) {
            float4 v = *(const float4*)&tile[l * 36 + cb + 4 * j];
            c[4*j] = v.x; c[4*j+1] = v.y; c[4*j+2] = v.z; c[4*j+3] = v.w;
        }
    }
    const float lf_edge = (w2 == 0) ? c[0]  : tile[l * 36 + 15];  // col -1 replicates
    const float rt_edge = (w2 == 1) ? c[15] : tile[l * 36 + 16];  // col 32 replicates
    __syncthreads();                  // all tile reads done before overlay destroyed

    // ---- zero hist: 2304 floats = 576 float4 over 64 patch-threads ----
    {
        float4 z = make_float4(0.f, 0.f, 0.f, 0.f);
        #pragma unroll
        for (int j = 0; j < 9; ++j)
            *(float4*)&hist[(tt + 64 * j) << 2] = z;
    }
    __syncthreads();                  // zeroed before scatter

    // ---- main loop: 2 chunks x 8 px; compute unconditional, RMW predicated ----
    const int colw = (w2 << 5) + l;   // private hist column (bank = lane)
    #pragma unroll
    for (int k = 0; k < 2; ++k) {
        float4 ga = *(const float4*)&gksm[l * 36 + 16 * w2 + 8 * k];
        float4 gb = *(const float4*)&gksm[l * 36 + 16 * w2 + 8 * k + 4];
        float gg[8] = {ga.x, ga.y, ga.z, ga.w, gb.x, gb.y, gb.z, gb.w};
        #pragma unroll
        for (int i = 0; i < 8; ++i) {
            const int q = 8 * k + i;  // local col 0..15
            float up = __shfl_up_sync(FULLM, c[q], 1);    // lane 0 -> self (replicate)
            float dn = __shfl_down_sync(FULLM, c[q], 1);  // lane 31 -> self
            float lf = (q > 0)  ? c[q - 1] : lf_edge;
            float rt = (q < 15) ? c[q + 1] : rt_edge;
            float gx = __fadd_rn(__fmul_rn(w0x, lf), __fmul_rn(w2x, rt));
            if (!fx) gx = __fadd_rn(__fadd_rn(__fmul_rn(w0x, lf),
                                              __fmul_rn(w1x, c[q])),
                                    __fmul_rn(w2x, rt));
            float gy = __fadd_rn(__fmul_rn(w0y, up), __fmul_rn(w2y, dn));
            if (!fy) gy = __fadd_rn(__fadd_rn(__fmul_rn(w0y, up),
                                              __fmul_rn(w1y, c[q])),
                                    __fmul_rn(w2y, dn));
            float s  = __fadd_rn(__fadd_rn(__fmul_rn(gx, gx), __fmul_rn(gy, gy)),
                                 1e-10f);
            float m  = __fmul_rn(sqrt_approx(s), gg[i]);

            float o = atan2f(gy, gx);                     // bit-exact libdevice path
            if (o < 0.f) o = __fadd_rn(o, TWO_PI_F);      // jnp.mod(ori, 2pi)
            // ob = RN( RN(36*o) / 2pi ) via Markstein (== div.rn bit-exactly):
            float xx = __fmul_rn(36.f, o);
            float y0 = __fmul_rn(xx, rcp2pi);
            float ee = __fmaf_rn(-TWO_PI_F, y0, xx);      // exact residual
            float ob = __fmaf_rn(ee, rcp2pi, y0);         // correctly rounded quotient
            int   b  = __float2int_rd(ob);                // floor (ob >= 0)
            float bf = __int2float_rn(b);                 // exact for 0..36
            if (b > NBINS - 1) b -= NBINS;                // ob == 36.0 edge
            float wgt = __fmul_rn(__fsub_rn(1.f, __fsub_rn(ob, bf)), m);
            const int a = b * HW + colw;

            if (m > 0.001f)                               // short arm -> @P predication
                hist[a] = __fadd_rn(hist[a], wgt);
        }
    }
    __syncthreads();

    // ---- reduction: each half sums its own 32 columns (diagonal, conflict-free) ----
    {
        float s = 0.f, e = 0.f;
        #pragma unroll
        for (int cc = 0; cc < 32; ++cc)
            s = __fadd_rn(s, hist[l * HW + (w2 << 5) + ((l + cc) & 31)]);
        if (l < 4) {
            #pragma unroll
            for (int cc = 0; cc < 32; ++cc)
                e = __fadd_rn(e, hist[(32 + l) * HW + (w2 << 5) + ((l + cc) & 31)]);
        }
        scratch[pw][w2][l] = s;
        if (l < 4) scratch[pw][w2][32 + l] = e;
    }
    __syncthreads();

    // ---- epilogue on half 0 of each patch ----
    if (w2 == 0) {
        float s = __fmul_rn(__fadd_rn(scratch[pw][0][l], scratch[pw][1][l]),
                            0.0009765625f);               // /1024 exact
        float e = 0.f;
        if (l < 4)
            e = __fmul_rn(__fadd_rn(scratch[pw][0][32 + l], scratch[pw][1][32 + l]),
                          0.0009765625f);

        float hm  = __shfl_up_sync(FULLM, s, 1);
        float hp  = __shfl_down_sync(FULLM, s, 1);
        float e0  = __shfl_sync(FULLM, e, 0);
        float s31 = __shfl_sync(FULLM, s, 31);
        float em  = __shfl_up_sync(FULLM, e, 1);
        float ep  = __shfl_down_sync(FULLM, e, 1);
        if (l == 0)  hm = 0.f;            // zero pad left
        if (l == 31) hp = e0;             // h[32]
        float v1 = __fadd_rn(__fadd_rn(__fmul_rn(m0, hm), __fmul_rn(m1, s)),
                             __fmul_rn(m2, hp));
        int i1 = l;
        if (l < 4) {                      // bins 32..35
            float hm2 = (l == 0) ? s31 : em;
            float hp2 = (l == 3) ? 0.f : ep;
            float v2 = __fadd_rn(__fadd_rn(__fmul_rn(m0, hm2), __fmul_rn(m1, e)),
                                 __fmul_rn(m2, hp2));
            if (v2 > v1) { v1 = v2; i1 = 32 + l; }   // tie keeps smaller index
        }
        #pragma unroll
        for (int off = 16; off > 0; off >>= 1) {
            float ov = __shfl_xor_sync(FULLM, v1, off);
            int   oi = __shfl_xor_sync(FULLM, i1, off);
            if (ov > v1 || (ov == v1 && oi < i1)) { v1 = ov; i1 = oi; }
        }
        if (l == 0 && p < B) {
            float fi = (float)i1;
            out[p] = -__fsub_rn(__fdiv_rn(__fmul_rn(TWO_PI_F, fi), 36.f), PI_F);
        }
    }
}

extern "C" void kernel_launch(void* const* d_in, const int* in_sizes, int n_in,
                              void* d_out, int out_size)
{
    const float* x   = (const float*)d_in[0];
    const float* gxw = (const float*)d_in[1];
    const float* gyw = (const float*)d_in[2];
    const float* smw = (const float*)d_in[3];
    const float* gk  = (const float*)d_in[4];
    float* out = (float*)d_out;

    int B = in_sizes[0] / (PS * PS);
    int grid = (B + 1) / 2;
    OrientationFinder_83193516523885_kernel<<<grid, BLK>>>(x, gxw, gyw, smw, gk, out, B);
}

// round 13
// speedup vs baseline: 1.4427x; 1.1289x over previous
#include <cuda_runtime.h>
#include <cuda_bf16.h>

#define NBINS 36
#define PS 32
#define BLK 128
#define HW 64                    // hist width: 2 column-halves x 32 lanes
#define TWO_PI_F 6.2831855f      // f32(2*pi)
#define PI_F     3.1415927f      // f32(pi)
#define FULLM 0xffffffffu

typedef unsigned long long ull;

__device__ __forceinline__ float sqrt_approx(float x) {
    float r; asm("sqrt.approx.f32 %0,%1;" : "=f"(r) : "f"(x)); return r;
}
__device__ __forceinline__ ull f2_add(ull a, ull b) {
    ull r; asm("add.rn.f32x2 %0,%1,%2;" : "=l"(r) : "l"(a), "l"(b)); return r;
}
__device__ __forceinline__ void unpackf2(ull v, float& a, float& b) {
    asm("mov.b64 {%0,%1},%2;" : "=f"(a), "=f"(b) : "l"(v));
}

__global__ __launch_bounds__(BLK, 9)   // 56-reg cap; smem ~23.6KB; 1 barrier slot
void OrientationFinder_83193516523885_kernel(
    const float* __restrict__ x,
    const float* __restrict__ gxw,
    const float* __restrict__ gyw,
    const float* __restrict__ smw,
    const float* __restrict__ gk,
    float* __restrict__ out,
    int B)
{
    __shared__ __align__(16) float gksm[PS * 36];        // gk, padded stride 36
    __shared__ __align__(16) float hist2[2][NBINS * HW]; // per-patch hist (tile overlaid)
    __shared__ float scratch[2][2][40];                  // [patch][half][bin] partials

    const int t  = threadIdx.x;
    const int pw = t >> 6;            // patch within block (0..1)
    const int tt = t & 63;            // thread within patch
    const int w2 = tt >> 5;           // column-half (0..1)
    const int l  = t & 31;            // lane = row

    // ---- cooperative gk staging (all 128 threads, coalesced) ----
    {
        const float4* g4 = (const float4*)gk;
        #pragma unroll
        for (int j = 0; j < 2; ++j) {
            int m = t + BLK * j;
            float4 v = g4[m];
            *(float4*)&gksm[(m >> 3) * 36 + ((m & 7) << 2)] = v;
        }
    }

    const long long p = (long long)blockIdx.x * 2 + pw;
    float* hist = hist2[pw];

    // ---- coalesced global load: 64 threads x 4 float4 = one patch ----
    float4 vb[4];
    if (p < B) {
        const float4* xv = (const float4*)(x + p * (PS * PS));
        #pragma unroll
        for (int j = 0; j < 4; ++j) vb[j] = xv[tt + 64 * j];
    }
    const float w0x = gxw[0], w1x = gxw[1], w2x = gxw[2];
    const float w0y = gyw[0], w1y = gyw[1], w2y = gyw[2];
    const float m0 = smw[0], m1 = smw[1], m2 = smw[2];
    const bool fx = (w1x == 0.0f);    // uniform fast-path (bit-safe, see prior rounds)
    const bool fy = (w1y == 0.0f);
    // Markstein exactly-rounded constant division setup: r = RN(1/2pi), once.
    const float rcp2pi = __fdiv_rn(1.0f, TWO_PI_F);

    // ---- redistribute to row-major tile (overlaid on hist; 1152 < 2304 floats) ----
    float* tile = hist;               // stride-36 rows
    if (p < B) {
        #pragma unroll
        for (int j = 0; j < 4; ++j) {
            int m = tt + 64 * j;
            *(float4*)&tile[(m >> 3) * 36 + ((m & 7) << 2)] = vb[j];
        }
    }
    __syncthreads();                  // tile writes + gksm visible

    // ---- lane reads its 16-column strip of row l, plus the 2 edge scalars ----
    float c[16];
    {
        const int cb = 16 * w2;       // global col base
        #pragma unroll
        for (int j = 0; j < 4; ++j) {
            float4 v = *(const float4*)&tile[l * 36 + cb + 4 * j];
            c[4*j] = v.x; c[4*j+1] = v.y; c[4*j+2] = v.z; c[4*j+3] = v.w;
        }
    }
    const float lf_edge = (w2 == 0) ? c[0]  : tile[l * 36 + 15];  // col -1 replicates
    const float rt_edge = (w2 == 1) ? c[15] : tile[l * 36 + 16];  // col 32 replicates
    __syncthreads();                  // all tile reads done before overlay destroyed

    // ---- zero hist: 2304 floats = 576 float4 over 64 patch-threads ----
    {
        float4 z = make_float4(0.f, 0.f, 0.f, 0.f);
        #pragma unroll
        for (int j = 0; j < 9; ++j)
            *(float4*)&hist[(tt + 64 * j) << 2] = z;
    }
    __syncthreads();                  // zeroed before scatter

    // ---- main loop: 2 chunks x 8 px; compute unconditional, RMW predicated ----
    const int colw = (w2 << 5) + l;   // private hist column (bank = lane)
    #pragma unroll
    for (int k = 0; k < 2; ++k) {
        float4 ga = *(const float4*)&gksm[l * 36 + 16 * w2 + 8 * k];
        float4 gb = *(const float4*)&gksm[l * 36 + 16 * w2 + 8 * k + 4];
        float gg[8] = {ga.x, ga.y, ga.z, ga.w, gb.x, gb.y, gb.z, gb.w};
        #pragma unroll
        for (int i = 0; i < 8; ++i) {
            // patch col 0 has gk == 0.0 exactly (outside inscribed circle):
            // every lane masked -> skip whole pixel; warp-uniform branch (w2).
            if (k == 0 && i == 0 && w2 == 0) continue;

            const int q = 8 * k + i;  // local col 0..15
            float up = __shfl_up_sync(FULLM, c[q], 1);    // lane 0 -> self (replicate)
            float dn = __shfl_down_sync(FULLM, c[q], 1);  // lane 31 -> self
            float lf = (q > 0)  ? c[q - 1] : lf_edge;
            float rt = (q < 15) ? c[q + 1] : rt_edge;
            float gx = __fadd_rn(__fmul_rn(w0x, lf), __fmul_rn(w2x, rt));
            if (!fx) gx = __fadd_rn(__fadd_rn(__fmul_rn(w0x, lf),
                                              __fmul_rn(w1x, c[q])),
                                    __fmul_rn(w2x, rt));
            float gy = __fadd_rn(__fmul_rn(w0y, up), __fmul_rn(w2y, dn));
            if (!fy) gy = __fadd_rn(__fadd_rn(__fmul_rn(w0y, up),
                                              __fmul_rn(w1y, c[q])),
                                    __fmul_rn(w2y, dn));
            // s feeds only the approx sqrt + threshold -> FMA fusion is safe
            float s = __fmaf_rn(gx, gx, __fmaf_rn(gy, gy, 1e-10f));
            float m = __fmul_rn(sqrt_approx(s), gg[i]);

            float o = atan2f(gy, gx);                     // bit-exact libdevice path
            if (o < 0.f) o = __fadd_rn(o, TWO_PI_F);      // jnp.mod(ori, 2pi)
            // ob = RN( RN(36*o) / 2pi ) via Markstein (== div.rn bit-exactly):
            float xx = __fmul_rn(36.f, o);
            float y0 = __fmul_rn(xx, rcp2pi);
            float ee = __fmaf_rn(-TWO_PI_F, y0, xx);      // exact residual
            float ob = __fmaf_rn(ee, rcp2pi, y0);         // correctly rounded quotient
            int   b  = __float2int_rd(ob);                // floor (ob >= 0)
            float bf = __int2float_rn(b);                 // exact for 0..36
            if (b > NBINS - 1) b -= NBINS;                // ob == 36.0 edge
            float wo1 = __fsub_rn(ob, bf);
            float wgt = __fmaf_rn(-wo1, m, m);            // (1-wo1)*m, weight-only effect
            const int a = b * HW + colw;

            if (m > 0.001f)                               // short arm -> @P predication
                hist[a] = __fadd_rn(hist[a], wgt);
        }
    }
    __syncthreads();

    // ---- reduction: packed f32x2, LDS.128, diagonal group offset (g+l)&7 ----
    {
        const float* rowp = hist + l * HW + (w2 << 5);
        ull a0, a1;
        {
            ulonglong2 e = *(const ulonglong2*)(rowp + 4 * (l & 7));
            a0 = e.x; a1 = e.y;
        }
        #pragma unroll
        for (int g = 1; g < 8; ++g) {
            ulonglong2 e = *(const ulonglong2*)(rowp + 4 * ((g + l) & 7));
            a0 = f2_add(a0, e.x);
            a1 = f2_add(a1, e.y);
        }
        a0 = f2_add(a0, a1);
        float fa, fb; unpackf2(a0, fa, fb);
        scratch[pw][w2][l] = __fadd_rn(fa, fb);

        if (l < 4) {                  // bins 32..35
            const float* rp2 = hist + (32 + l) * HW + (w2 << 5);
            ull b0, b1;
            {
                ulonglong2 e = *(const ulonglong2*)(rp2 + 4 * (l & 7));
                b0 = e.x; b1 = e.y;
            }
            #pragma unroll
            for (int g = 1; g < 8; ++g) {
                ulonglong2 e = *(const ulonglong2*)(rp2 + 4 * ((g + l) & 7));
                b0 = f2_add(b0, e.x);
                b1 = f2_add(b1, e.y);
            }
            b0 = f2_add(b0, b1);
            float ga2, gb2; unpackf2(b0, ga2, gb2);
            scratch[pw][w2][32 + l] = __fadd_rn(ga2, gb2);
        }
    }
    __syncthreads();

    // ---- epilogue on half 0 of each patch ----
    if (w2 == 0) {
        float s = __fmul_rn(__fadd_rn(scratch[pw][0][l], scratch[pw][1][l]),
                            0.0009765625f);               // /1024 exact
        float e = 0.f;
        if (l < 4)
            e = __fmul_rn(__fadd_rn(scratch[pw][0][32 + l], scratch[pw][1][32 + l]),
                          0.0009765625f);

        float hm  = __shfl_up_sync(FULLM, s, 1);
        float hp  = __shfl_down_sync(FULLM, s, 1);
        float e0  = __shfl_sync(FULLM, e, 0);
        float s31 = __shfl_sync(FULLM, s, 31);
        float em  = __shfl_up_sync(FULLM, e, 1);
        float ep  = __shfl_down_sync(FULLM, e, 1);
        if (l == 0)  hm = 0.f;            // zero pad left
        if (l == 31) hp = e0;             // h[32]
        float v1 = __fadd_rn(__fadd_rn(__fmul_rn(m0, hm), __fmul_rn(m1, s)),
                             __fmul_rn(m2, hp));
        int i1 = l;
        if (l < 4) {                      // bins 32..35
            float hm2 = (l == 0) ? s31 : em;
            float hp2 = (l == 3) ? 0.f : ep;
            float v2 = __fadd_rn(__fadd_rn(__fmul_rn(m0, hm2), __fmul_rn(m1, e)),
                                 __fmul_rn(m2, hp2));
            if (v2 > v1) { v1 = v2; i1 = 32 + l; }   // tie keeps smaller index
        }
        #pragma unroll
        for (int off = 16; off > 0; off >>= 1) {
            float ov = __shfl_xor_sync(FULLM, v1, off);
            int   oi = __shfl_xor_sync(FULLM, i1, off);
            if (ov > v1 || (ov == v1 && oi < i1)) { v1 = ov; i1 = oi; }
        }
        if (l == 0 && p < B) {
            float fi = (float)i1;
            out[p] = -__fsub_rn(__fdiv_rn(__fmul_rn(TWO_PI_F, fi), 36.f), PI_F);
        }
    }
}

extern "C" void kernel_launch(void* const* d_in, const int* in_sizes, int n_in,
                              void* d_out, int out_size)
{
    const float* x   = (const float*)d_in[0];
    const float* gxw = (const float*)d_in[1];
    const float* gyw = (const float*)d_in[2];
    const float* smw = (const float*)d_in[3];
    const float* gk  = (const float*)d_in[4];
    float* out = (float*)d_out;

    int B = in_sizes[0] / (PS * PS);
    int grid = (B + 1) / 2;
    OrientationFinder_83193516523885_kernel<<<grid, BLK>>>(x, gxw, gyw, smw, gk, out, B);
}

// round 14
// speedup vs baseline: 1.5272x; 1.0586x over previous
#include <cuda_runtime.h>
#include <cuda_bf16.h>

#define NBINS 36
#define PS 32
#define BLK 128
#define HW 64                    // hist width: 2 column-halves x 32 lanes
#define TWO_PI_F 6.2831855f      // f32(2*pi)
#define PI_F     3.1415927f      // f32(pi)
#define FULLM 0xffffffffu

typedef unsigned long long ull;

__device__ __forceinline__ float sqrt_approx(float x) {
    float r; asm("sqrt.approx.f32 %0,%1;" : "=f"(r) : "f"(x)); return r;
}
__device__ __forceinline__ ull f2_add(ull a, ull b) {
    ull r; asm("add.rn.f32x2 %0,%1,%2;" : "=l"(r) : "l"(a), "l"(b)); return r;
}
__device__ __forceinline__ void unpackf2(ull v, float& a, float& b) {
    asm("mov.b64 {%0,%1},%2;" : "=f"(a), "=f"(b) : "l"(v));
}

__global__ __launch_bounds__(BLK, 9)   // 56-reg cap; smem ~23.6KB; 1 barrier slot
void OrientationFinder_83193516523885_kernel(
    const float* __restrict__ x,
    const float* __restrict__ gxw,
    const float* __restrict__ gyw,
    const float* __restrict__ smw,
    const float* __restrict__ gk,
    float* __restrict__ out,
    int B)
{
    __shared__ __align__(16) float gksm[PS * 36];        // 0.5*gk, padded stride 36
    __shared__ __align__(16) float hist2[2][NBINS * HW]; // per-patch hist (tile overlaid)
    __shared__ float scratch[2][2][40];                  // [patch][half][bin] partials

    const int t  = threadIdx.x;
    const int pw = t >> 6;            // patch within block (0..1)
    const int tt = t & 63;            // thread within patch
    const int w2 = tt >> 5;           // column-half (0..1)
    const int l  = t & 31;            // lane = row

    // ---- cooperative gk staging, pre-scaled by exact 0.5 ----
    {
        const float4* g4 = (const float4*)gk;
        #pragma unroll
        for (int j = 0; j < 2; ++j) {
            int m = t + BLK * j;
            float4 v = g4[m];
            v.x = __fmul_rn(v.x, 0.5f); v.y = __fmul_rn(v.y, 0.5f);
            v.z = __fmul_rn(v.z, 0.5f); v.w = __fmul_rn(v.w, 0.5f);
            *(float4*)&gksm[(m >> 3) * 36 + ((m & 7) << 2)] = v;
        }
    }

    const long long p = (long long)blockIdx.x * 2 + pw;
    float* hist = hist2[pw];

    // ---- coalesced global load: 64 threads x 4 float4 = one patch ----
    float4 vb[4];
    if (p < B) {
        const float4* xv = (const float4*)(x + p * (PS * PS));
        #pragma unroll
        for (int j = 0; j < 4; ++j) vb[j] = xv[tt + 64 * j];
    }
    const float w0x = gxw[0], w1x = gxw[1], w2x = gxw[2];
    const float w0y = gyw[0], w1y = gyw[1], w2y = gyw[2];
    const float m0 = smw[0], m1 = smw[1], m2 = smw[2];
    // exact-scale fast path: gx = 0.5*(lf-rt), gy = 0.5*(up-dn); 0.5-scaling is
    // exact => atan2f(dy,dx) bit-identical to atan2f(gy,gx). Uniform guard.
    const bool fastg = (w0x == 0.5f && w1x == 0.0f && w2x == -0.5f &&
                        w0y == 0.5f && w1y == 0.0f && w2y == -0.5f);
    // Markstein exactly-rounded constant division setup: r = RN(1/2pi), once.
    const float rcp2pi = __fdiv_rn(1.0f, TWO_PI_F);
    const float EPS4 = 4e-10f;        // exact 4x of 1e-10 eps (power-of-2 scale)

    // ---- redistribute to row-major tile (overlaid on hist; 1152 < 2304 floats) ----
    float* tile = hist;               // stride-36 rows
    if (p < B) {
        #pragma unroll
        for (int j = 0; j < 4; ++j) {
            int m = tt + 64 * j;
            *(float4*)&tile[(m >> 3) * 36 + ((m & 7) << 2)] = vb[j];
        }
    }
    __syncthreads();                  // tile writes + gksm visible

    // ---- lane reads its 16-column strip of row l, plus the 2 edge scalars ----
    float c[16];
    {
        const int cb = 16 * w2;       // global col base
        #pragma unroll
        for (int j = 0; j < 4; ++j) {
            float4 v = *(const float4*)&tile[l * 36 + cb + 4 * j];
            c[4*j] = v.x; c[4*j+1] = v.y; c[4*j+2] = v.z; c[4*j+3] = v.w;
        }
    }
    const float lf_edge = (w2 == 0) ? c[0]  : tile[l * 36 + 15];  // col -1 replicates
    const float rt_edge = (w2 == 1) ? c[15] : tile[l * 36 + 16];  // col 32 replicates
    __syncthreads();                  // all tile reads done before overlay destroyed

    // ---- zero hist: 2304 floats = 576 float4 over 64 patch-threads ----
    {
        float4 z = make_float4(0.f, 0.f, 0.f, 0.f);
        #pragma unroll
        for (int j = 0; j < 9; ++j)
            *(float4*)&hist[(tt + 64 * j) << 2] = z;
    }
    __syncthreads();                  // zeroed before scatter

    // ---- main loop: 2 chunks x 8 px; compute unconditional, RMW predicated ----
    const int colw = (w2 << 5) + l;   // private hist column (bank = lane)
    #pragma unroll
    for (int k = 0; k < 2; ++k) {
        float4 ga = *(const float4*)&gksm[l * 36 + 16 * w2 + 8 * k];
        float4 gb = *(const float4*)&gksm[l * 36 + 16 * w2 + 8 * k + 4];
        float gh[8] = {ga.x, ga.y, ga.z, ga.w, gb.x, gb.y, gb.z, gb.w};  // 0.5*gk
        #pragma unroll
        for (int i = 0; i < 8; ++i) {
            // patch col 0 has gk == 0.0 exactly -> whole pixel dead; uniform skip
            if (k == 0 && i == 0 && w2 == 0) continue;

            const int q = 8 * k + i;  // local col 0..15
            float up = __shfl_up_sync(FULLM, c[q], 1);    // lane 0 -> self (replicate)
            float dn = __shfl_down_sync(FULLM, c[q], 1);  // lane 31 -> self
            float lf = (q > 0)  ? c[q - 1] : lf_edge;
            float rt = (q < 15) ? c[q + 1] : rt_edge;
            float dx = __fsub_rn(lf, rt);                 // 2*gx (exact relation)
            float dy = __fsub_rn(up, dn);                 // 2*gy

            float ax, ay, m;
            if (fastg) {
                ax = dx; ay = dy;                         // atan2 scale-invariant
                // m = sqrt(0.25*(dx^2+dy^2+4eps))*gk = sqrt(u)*(0.5*gk); continuous
                float u = __fmaf_rn(dx, dx, __fmaf_rn(dy, dy, EPS4));
                m = __fmul_rn(sqrt_approx(u), gh[i]);
            } else {                                      // generic (never taken here)
                float gx = __fadd_rn(__fadd_rn(__fmul_rn(w0x, lf),
                                               __fmul_rn(w1x, c[q])),
                                     __fmul_rn(w2x, rt));
                float gy = __fadd_rn(__fadd_rn(__fmul_rn(w0y, up),
                                               __fmul_rn(w1y, c[q])),
                                     __fmul_rn(w2y, dn));
                ax = gx; ay = gy;
                float s = __fmaf_rn(gx, gx, __fmaf_rn(gy, gy, 1e-10f));
                m = __fmul_rn(sqrt_approx(s), __fmul_rn(2.0f, gh[i]));
            }

            float o = atan2f(ay, ax);                     // bit-exact libdevice path
            if (o < 0.f) o = __fadd_rn(o, TWO_PI_F);      // jnp.mod(ori, 2pi)
            // ob = RN( RN(36*o) / 2pi ) via Markstein (== div.rn bit-exactly):
            float xx = __fmul_rn(36.f, o);
            float y0 = __fmul_rn(xx, rcp2pi);
            float ee = __fmaf_rn(-TWO_PI_F, y0, xx);      // exact residual
            float ob = __fmaf_rn(ee, rcp2pi, y0);         // correctly rounded quotient
            int   b  = __float2int_rd(ob);                // floor (ob >= 0)
            float bf = __int2float_rn(b);                 // exact for 0..36
            if (b > NBINS - 1) b -= NBINS;                // ob == 36.0 edge
            float wo1 = __fsub_rn(ob, bf);
            float wgt = __fmaf_rn(-wo1, m, m);            // (1-wo1)*m, weight-only
            const int a = b * HW + colw;

            if (m > 0.001f)                               // short arm -> @P predication
                hist[a] = __fadd_rn(hist[a], wgt);
        }
    }
    __syncthreads();

    // ---- reduction: packed f32x2, LDS.128, diagonal group offset (g+l)&7 ----
    {
        const float* rowp = hist + l * HW + (w2 << 5);
        ull a0, a1;
        {
            ulonglong2 e = *(const ulonglong2*)(rowp + 4 * (l & 7));
            a0 = e.x; a1 = e.y;
        }
        #pragma unroll
        for (int g = 1; g < 8; ++g) {
            ulonglong2 e = *(const ulonglong2*)(rowp + 4 * ((g + l) & 7));
            a0 = f2_add(a0, e.x);
            a1 = f2_add(a1, e.y);
        }
        a0 = f2_add(a0, a1);
        float fa, fb; unpackf2(a0, fa, fb);
        scratch[pw][w2][l] = __fadd_rn(fa, fb);

        if (l < 4) {                  // bins 32..35
            const float* rp2 = hist + (32 + l) * HW + (w2 << 5);
            ull b0, b1;
            {
                ulonglong2 e = *(const ulonglong2*)(rp2 + 4 * (l & 7));
                b0 = e.x; b1 = e.y;
            }
            #pragma unroll
            for (int g = 1; g < 8; ++g) {
                ulonglong2 e = *(const ulonglong2*)(rp2 + 4 * ((g + l) & 7));
                b0 = f2_add(b0, e.x);
                b1 = f2_add(b1, e.y);
            }
            b0 = f2_add(b0, b1);
            float ga2, gb2; unpackf2(b0, ga2, gb2);
            scratch[pw][w2][32 + l] = __fadd_rn(ga2, gb2);
        }
    }
    __syncthreads();

    // ---- epilogue on half 0 of each patch ----
    if (w2 == 0) {
        float s = __fmul_rn(__fadd_rn(scratch[pw][0][l], scratch[pw][1][l]),
                            0.0009765625f);               // /1024 exact
        float e = 0.f;
        if (l < 4)
            e = __fmul_rn(__fadd_rn(scratch[pw][0][32 + l], scratch[pw][1][32 + l]),
                          0.0009765625f);

        float hm  = __shfl_up_sync(FULLM, s, 1);
        float hp  = __shfl_down_sync(FULLM, s, 1);
        float e0  = __shfl_sync(FULLM, e, 0);
        float s31 = __shfl_sync(FULLM, s, 31);
        float em  = __shfl_up_sync(FULLM, e, 1);
        float ep  = __shfl_down_sync(FULLM, e, 1);
        if (l == 0)  hm = 0.f;            // zero pad left
        if (l == 31) hp = e0;             // h[32]
        float v1 = __fadd_rn(__fadd_rn(__fmul_rn(m0, hm), __fmul_rn(m1, s)),
                             __fmul_rn(m2, hp));
        int i1 = l;
        if (l < 4) {                      // bins 32..35
            float hm2 = (l == 0) ? s31 : em;
            float hp2 = (l == 3) ? 0.f : ep;
            float v2 = __fadd_rn(__fadd_rn(__fmul_rn(m0, hm2), __fmul_rn(m1, e)),
                                 __fmul_rn(m2, hp2));
            if (v2 > v1) { v1 = v2; i1 = 32 + l; }   // tie keeps smaller index
        }
        #pragma unroll
        for (int off = 16; off > 0; off >>= 1) {
            float ov = __shfl_xor_sync(FULLM, v1, off);
            int   oi = __shfl_xor_sync(FULLM, i1, off);
            if (ov > v1 || (ov == v1 && oi < i1)) { v1 = ov; i1 = oi; }
        }
        if (l == 0 && p < B) {
            float fi = (float)i1;
            out[p] = -__fsub_rn(__fdiv_rn(__fmul_rn(TWO_PI_F, fi), 36.f), PI_F);
        }
    }
}

extern "C" void kernel_launch(void* const* d_in, const int* in_sizes, int n_in,
                              void* d_out, int out_size)
{
    const float* x   = (const float*)d_in[0];
    const float* gxw = (const float*)d_in[1];
    const float* gyw = (const float*)d_in[2];
    const float* smw = (const float*)d_in[3];
    const float* gk  = (const float*)d_in[4];
    float* out = (float*)d_out;

    int B = in_sizes[0] / (PS * PS);
    int grid = (B + 1) / 2;
    OrientationFinder_83193516523885_kernel<<<grid, BLK>>>(x, gxw, gyw, smw, gk, out, B);
}